// round 11
// baseline (speedup 1.0000x reference)
#include <cuda_runtime.h>
#include <cstdint>

// ---------------------------------------------------------------------------
// GAT hierarchical 2-layer. R11: revert elog fusion (R6 dataflow), keep
// compile-time-E attention bodies, vectorize alpha loads (LDS.128 broadcast),
// re-tile tail GEMMs to 32x64 (2x block count; they were block-starved).
// ---------------------------------------------------------------------------

// scratch layout (floats)
static constexpr size_t OFF_Y1 = 0;                        // [10240,512]
static constexpr size_t OFF_Y0 = OFF_Y1 + 10240ull * 512;  // [1024,512]
static constexpr size_t OFF_U  = OFF_Y0 + 1024ull * 512;   // [1024,2048]
static constexpr size_t OFF_H  = OFF_U  + 1024ull * 2048;  // [1024,512]
static constexpr size_t OFF_P0 = OFF_H  + 1024ull * 512;   // P0s[512],P0n[512]
static constexpr size_t OFF_Q  = OFF_P0 + 1024;            // Qs[2048],Qn[2048]
static constexpr size_t OFF_N  = OFF_Q  + 4096;            // N[4][512][128]
static constexpr size_t SCRATCH_FLOATS = OFF_N + 4ull * 512 * 128;

__device__ float g_scratch[SCRATCH_FLOATS];

static __device__ __forceinline__ float4 ldg4(const float* p) {
    return __ldg((const float4*)p);
}
static __device__ __forceinline__ float dot4(float4 a, float4 b, float acc) {
    acc = fmaf(a.x, b.x, acc);
    acc = fmaf(a.y, b.y, acc);
    acc = fmaf(a.z, b.z, acc);
    acc = fmaf(a.w, b.w, acc);
    return acc;
}
static __device__ __forceinline__ uint32_t smem_u32(const void* p) {
    return (uint32_t)__cvta_generic_to_shared(p);
}
static __device__ __forceinline__ void mbar_init(uint32_t mbar, uint32_t cnt) {
    asm volatile("mbarrier.init.shared.b64 [%0], %1;" :: "r"(mbar), "r"(cnt) : "memory");
}
static __device__ __forceinline__ void mbar_expect_tx(uint32_t mbar, uint32_t bytes) {
    asm volatile("mbarrier.arrive.expect_tx.shared.b64 _, [%0], %1;"
                 :: "r"(mbar), "r"(bytes) : "memory");
}
static __device__ __forceinline__ void bulk_g2s(uint32_t dst, const void* src,
                                                uint32_t bytes, uint32_t mbar) {
    asm volatile("cp.async.bulk.shared::cluster.global.mbarrier::complete_tx::bytes "
                 "[%0], [%1], %2, [%3];"
                 :: "r"(dst), "l"(src), "r"(bytes), "r"(mbar) : "memory");
}
static __device__ __forceinline__ void mbar_wait(uint32_t mbar, uint32_t parity) {
    asm volatile(
        "{\n\t.reg .pred P;\n"
        "W_%=:\n\t"
        "mbarrier.try_wait.parity.shared.b64 P, [%0], %1;\n\t"
        "@P bra D_%=;\n\t"
        "bra W_%=;\n"
        "D_%=:\n\t}"
        :: "r"(mbar), "r"(parity) : "memory");
}
static __device__ __forceinline__ float4 lds4(const float* p) {
    float4 v;
    asm volatile("ld.shared.v4.f32 {%0,%1,%2,%3}, [%4];"
                 : "=f"(v.x), "=f"(v.y), "=f"(v.z), "=f"(v.w)
                 : "r"(smem_u32(p)));
    return v;
}

// ---------------------------------------------------------------------------
// prepN (32x32 tiles), unchanged.
// ---------------------------------------------------------------------------
__global__ __launch_bounds__(256)
void prepN_kernel(const float* __restrict__ W0, const float* __restrict__ W1,
                  float* __restrict__ Nmat)
{
    const int z = blockIdx.z;
    const int hp = z >> 2, h = z & 3;
    const float* A = W0 + h * 128;
    const float* B = W1 + (size_t)(h * 128) * 512 + hp * 128;
    float* C = Nmat + (size_t)hp * 65536 + (size_t)(h * 128) * 128;

    const int M0 = blockIdx.y * 32;
    const int N0 = blockIdx.x * 32;
    const int tx = threadIdx.x & 15;
    const int ty = threadIdx.x >> 4;
    const int tid = threadIdx.x;

    __shared__ float As[16][32];
    __shared__ float Bs[16][32];

    float acc[2][2] = {{0.f, 0.f}, {0.f, 0.f}};

    for (int k0 = 0; k0 < 128; k0 += 16) {
        if (tid < 128) {
            int r = tid >> 2, c4 = (tid & 3) * 4;
            float4 av = *(const float4*)(A + (size_t)(M0 + r) * 512 + k0 + c4);
            As[c4 + 0][r] = av.x;
            As[c4 + 1][r] = av.y;
            As[c4 + 2][r] = av.z;
            As[c4 + 3][r] = av.w;
        } else {
            int t = tid - 128;
            int r = t >> 3, c4 = (t & 7) * 4;
            float4 bv = *(const float4*)(B + (size_t)(k0 + r) * 512 + N0 + c4);
            *(float4*)&Bs[r][c4] = bv;
        }
        __syncthreads();
        #pragma unroll
        for (int k = 0; k < 16; k++) {
            float a0 = As[k][ty * 2], a1 = As[k][ty * 2 + 1];
            float b0 = Bs[k][tx * 2], b1 = Bs[k][tx * 2 + 1];
            acc[0][0] = fmaf(a0, b0, acc[0][0]);
            acc[0][1] = fmaf(a0, b1, acc[0][1]);
            acc[1][0] = fmaf(a1, b0, acc[1][0]);
            acc[1][1] = fmaf(a1, b1, acc[1][1]);
        }
        __syncthreads();
    }
    #pragma unroll
    for (int i = 0; i < 2; i++)
        #pragma unroll
        for (int j = 0; j < 2; j++)
            C[(size_t)(M0 + ty * 2 + i) * 128 + N0 + tx * 2 + j] = acc[i][j];
}

// ---------------------------------------------------------------------------
// prepQP: Q = N @ a1 (exact) and P0 = W0_h @ a0. Unchanged.
// ---------------------------------------------------------------------------
__global__ __launch_bounds__(128)
void prepQP_kernel(const float* __restrict__ Nmat,
                   const float* __restrict__ a1s, const float* __restrict__ a1n,
                   const float* __restrict__ W0,
                   const float* __restrict__ a0s, const float* __restrict__ a0n,
                   float* __restrict__ Q, float* __restrict__ P0)
{
    const int b = blockIdx.x;
    const int tid = threadIdx.x;
    if (b < 16) {
        const int hp = b >> 2, h = b & 3;
        __shared__ float sa1s[128], sa1n[128];
        sa1s[tid] = a1s[hp * 128 + tid];
        sa1n[tid] = a1n[hp * 128 + tid];
        __syncthreads();
        const float* nrow = Nmat + (size_t)hp * 65536 + (size_t)(h * 128 + tid) * 128;
        float s = 0.f, n = 0.f;
        #pragma unroll 4
        for (int d = 0; d < 128; d++) {
            float nv = nrow[d];
            s = fmaf(nv, sa1s[d], s);
            n = fmaf(nv, sa1n[d], n);
        }
        Q[hp * 512 + h * 128 + tid] = s;
        Q[2048 + hp * 512 + h * 128 + tid] = n;
    } else {
        const int t = (b - 16) * 128 + tid;
        const int h = t >> 7, f = t & 127;
        const float* wrow = W0 + (size_t)f * 512 + h * 128;
        const float* as = a0s + h * 128;
        const float* an = a0n + h * 128;
        float s = 0.f, n = 0.f;
        #pragma unroll 4
        for (int d = 0; d < 128; d++) {
            float wv = wrow[d];
            s = fmaf(wv, as[d], s);
            n = fmaf(wv, an[d], n);
        }
        P0[t] = s;
        P0[512 + t] = n;
    }
}

// ---------------------------------------------------------------------------
// fp32 GEMM: 32(M) x 64(N) tile, BK=16, 256 threads, 2x4/thread,
// reg double-buffer. Doubles block count vs 64x64 (these GEMMs were
// block-starved: 64-128 blocks on 148 SMs).
// ---------------------------------------------------------------------------
__global__ __launch_bounds__(256)
void gemm_kernel(const float* __restrict__ A, const float* __restrict__ B,
                 float* __restrict__ C,
                 int K, int lda, int ldb, int ldc,
                 int offA, int offB, int offC)
{
    A += (size_t)blockIdx.z * offA;
    B += (size_t)blockIdx.z * offB;
    C += (size_t)blockIdx.z * offC;

    const int M0 = blockIdx.y * 32;
    const int N0 = blockIdx.x * 64;
    const int tid = threadIdx.x;
    const int tx = tid & 15;          // 0..15 -> 4 cols each
    const int ty = tid >> 4;          // 0..15 -> 2 rows each

    __shared__ float As[16][32];
    __shared__ float Bs[16][64];

    // A: 32 rows x 16 cols = 128 float4 (threads 0..127)
    const int ar = tid >> 2, ac = (tid & 3) * 4;
    // B: 16 rows x 64 cols = 256 float4 (all threads)
    const int br = tid >> 4, bc = (tid & 15) * 4;

    float acc[2][4];
    #pragma unroll
    for (int i = 0; i < 2; i++)
        #pragma unroll
        for (int j = 0; j < 4; j++) acc[i][j] = 0.f;

    const int nt = K >> 4;
    float4 av, bv;
    if (tid < 128) av = *(const float4*)(A + (size_t)(M0 + ar) * lda + ac);
    bv = *(const float4*)(B + (size_t)br * ldb + N0 + bc);

    for (int i = 0; i < nt; i++) {
        if (tid < 128) {
            As[ac + 0][ar] = av.x;
            As[ac + 1][ar] = av.y;
            As[ac + 2][ar] = av.z;
            As[ac + 3][ar] = av.w;
        }
        *(float4*)&Bs[br][bc] = bv;
        __syncthreads();

        if (i + 1 < nt) {
            int k0 = (i + 1) << 4;
            if (tid < 128) av = *(const float4*)(A + (size_t)(M0 + ar) * lda + k0 + ac);
            bv = *(const float4*)(B + (size_t)(k0 + br) * ldb + N0 + bc);
        }

        #pragma unroll
        for (int k = 0; k < 16; k++) {
            float a0 = As[k][ty * 2], a1 = As[k][ty * 2 + 1];
            float4 b4 = *(const float4*)&Bs[k][tx * 4];
            acc[0][0] = fmaf(a0, b4.x, acc[0][0]);
            acc[0][1] = fmaf(a0, b4.y, acc[0][1]);
            acc[0][2] = fmaf(a0, b4.z, acc[0][2]);
            acc[0][3] = fmaf(a0, b4.w, acc[0][3]);
            acc[1][0] = fmaf(a1, b4.x, acc[1][0]);
            acc[1][1] = fmaf(a1, b4.y, acc[1][1]);
            acc[1][2] = fmaf(a1, b4.z, acc[1][2]);
            acc[1][3] = fmaf(a1, b4.w, acc[1][3]);
        }
        __syncthreads();
    }

    #pragma unroll
    for (int i = 0; i < 2; i++) {
        float4 o = {acc[i][0], acc[i][1], acc[i][2], acc[i][3]};
        *(float4*)(C + (size_t)(M0 + ty * 2 + i) * ldc + N0 + tx * 4) = o;
    }
}

// ---------------------------------------------------------------------------
// F=128 attention body, compile-time E. No elog fusion (reverted).
// Alpha loads vectorized (LDS.128 broadcast).
// ---------------------------------------------------------------------------
template<int E>
static __device__ __forceinline__ void attn128_body(
    const float* __restrict__ gxn, const float* __restrict__ gxs,
    float* __restrict__ gy,
    const float* __restrict__ Ws, const float* __restrict__ Wn,
    float* sxn, float* slog, float* salpha, uint32_t mbar)
{
    const int tid  = threadIdx.x;
    const int w    = tid >> 5;
    const int lane = tid & 31;
    const int hh   = lane & 3;
    const int s    = lane >> 2;

    if (tid == 0) {
        mbar_expect_tx(mbar, (uint32_t)(E * 128 * 4));
        bulk_g2s(smem_u32(sxn), gxn, (uint32_t)(E * 128 * 4), mbar);
    }

    float4 wq[4];
    #pragma unroll
    for (int j = 0; j < 4; j++) wq[j] = ldg4(Wn + hh * 128 + 4 * (s + 8 * j));

    if (w == 0) {  // self logit from global while TMA lands
        float acc = 0.f;
        #pragma unroll
        for (int j = 0; j < 4; j++)
            acc = dot4(ldg4(gxs + 4 * (s + 8 * j)),
                       ldg4(Ws + hh * 128 + 4 * (s + 8 * j)), acc);
        acc += __shfl_xor_sync(0xffffffffu, acc, 4);
        acc += __shfl_xor_sync(0xffffffffu, acc, 8);
        acc += __shfl_xor_sync(0xffffffffu, acc, 16);
        if (lane < 4) slog[E * 4 + lane] = acc;
    }

    mbar_wait(mbar, 0);

    // neighbor logits: warp w handles e = w, w+4, ... (unrolled, independent)
    #pragma unroll
    for (int eb = 0; eb < (E + 3) / 4; eb++) {
        int e = eb * 4 + w;
        if (e < E) {
            const float* xp = &sxn[e * 128];
            float acc = 0.f;
            #pragma unroll
            for (int j = 0; j < 4; j++)
                acc = dot4(lds4(xp + 4 * (s + 8 * j)), wq[j], acc);
            acc += __shfl_xor_sync(0xffffffffu, acc, 4);
            acc += __shfl_xor_sync(0xffffffffu, acc, 8);
            acc += __shfl_xor_sync(0xffffffffu, acc, 16);
            if (lane < 4) slog[e * 4 + lane] = acc;
        }
    }
    __syncthreads();

    {   // softmax per head (warp w = head)
        float es = slog[E * 4 + w];
        float v;
        if (lane < E) {
            float l = es + slog[lane * 4 + w];
            v = (l >= 0.f) ? l : 0.2f * l;
        } else {
            v = -3.4e38f;
        }
        float m = v;
        #pragma unroll
        for (int o = 16; o; o >>= 1) m = fmaxf(m, __shfl_xor_sync(0xffffffffu, m, o));
        float p = (lane < E) ? __expf(v - m) : 0.f;
        float sum = p;
        #pragma unroll
        for (int o = 16; o; o >>= 1) sum += __shfl_xor_sync(0xffffffffu, sum, o);
        if (lane < E) salpha[lane * 4 + w] = p / sum;
    }
    __syncthreads();

    // aggregate: 2 LDS per e (one float4-broadcast alpha + one data scalar)
    float acc0 = 0.f, acc1 = 0.f, acc2 = 0.f, acc3 = 0.f;
    #pragma unroll
    for (int e = 0; e < E; e++) {
        float4 al = lds4(&salpha[e * 4]);
        float val = sxn[e * 128 + tid];
        acc0 = fmaf(al.x, val, acc0);
        acc1 = fmaf(al.y, val, acc1);
        acc2 = fmaf(al.z, val, acc2);
        acc3 = fmaf(al.w, val, acc3);
    }
    gy[0 * 128 + tid] = acc0;
    gy[1 * 128 + tid] = acc1;
    gy[2 * 128 + tid] = acc2;
    gy[3 * 128 + tid] = acc3;
}

__global__ __launch_bounds__(128)
void attn128_kernel(const float* __restrict__ h0, const float* __restrict__ h1,
                    const float* __restrict__ h2,
                    const float* __restrict__ Ws, const float* __restrict__ Wn,
                    float* __restrict__ y1, float* __restrict__ y0, int G1)
{
    __shared__ float sxn[25 * 128];
    __shared__ float slog[26 * 4];
    __shared__ float salpha[25 * 4];
    __shared__ uint64_t mbar_s;

    const int b = blockIdx.x;
    const uint32_t mbar = smem_u32(&mbar_s);
    if (threadIdx.x == 0) {
        mbar_init(mbar, 1);
        asm volatile("fence.proxy.async.shared::cta;" ::: "memory");
    }
    __syncthreads();

    if (b < G1) {
        attn128_body<25>(h2 + (size_t)b * 25 * 128, h1 + (size_t)b * 128,
                         y1 + (size_t)b * 512, Ws, Wn, sxn, slog, salpha, mbar);
    } else {
        const int g = b - G1;
        attn128_body<10>(h1 + (size_t)g * 10 * 128, h0 + (size_t)g * 128,
                         y0 + (size_t)g * 512, Ws, Wn, sxn, slog, salpha, mbar);
    }
}

// ---------------------------------------------------------------------------
// F=512, E=10 layer-1 attention (computes its own logits; R6 form),
// alpha loads vectorized.
// ---------------------------------------------------------------------------
__global__ __launch_bounds__(128)
void attn512_kernel(const float* __restrict__ xs, const float* __restrict__ xn,
                    const float* __restrict__ Ws, const float* __restrict__ Wn,
                    float* __restrict__ y)
{
    constexpr int E = 10, F = 512;
    __shared__ float sxn[E * F];
    __shared__ float slog[(E + 1) * 4];
    __shared__ float salpha[E * 4];
    __shared__ uint64_t mbar_s;

    const int g    = blockIdx.x;
    const int tid  = threadIdx.x;
    const int w    = tid >> 5;
    const int lane = tid & 31;
    const uint32_t mbar = smem_u32(&mbar_s);
    const float* gxn = xn + (size_t)g * E * F;
    const float* gxs = xs + (size_t)g * F;

    if (tid == 0) {
        mbar_init(mbar, 1);
        asm volatile("fence.proxy.async.shared::cta;" ::: "memory");
    }
    __syncthreads();
    if (tid == 0) {
        mbar_expect_tx(mbar, E * F * 4);
        bulk_g2s(smem_u32(sxn), gxn, E * F * 4, mbar);
    }

    // warp-per-head weights in registers
    float4 wq[4], wsq[4];
    #pragma unroll
    for (int j = 0; j < 4; j++) {
        wq[j]  = ldg4(Wn + w * F + 4 * (lane + 32 * j));
        wsq[j] = ldg4(Ws + w * F + 4 * (lane + 32 * j));
    }

    {   // self logit from global while TMA lands
        float acc = 0.f;
        #pragma unroll
        for (int j = 0; j < 4; j++)
            acc = dot4(ldg4(gxs + 4 * (lane + 32 * j)), wsq[j], acc);
        #pragma unroll
        for (int o = 16; o; o >>= 1) acc += __shfl_xor_sync(0xffffffffu, acc, o);
        if (lane == 0) slog[E * 4 + w] = acc;
    }

    mbar_wait(mbar, 0);

    #pragma unroll
    for (int e = 0; e < E; e++) {
        const float* xp = &sxn[e * F];
        float acc = 0.f;
        #pragma unroll
        for (int j = 0; j < 4; j++)
            acc = dot4(lds4(xp + 4 * (lane + 32 * j)), wq[j], acc);
        #pragma unroll
        for (int o = 16; o; o >>= 1) acc += __shfl_xor_sync(0xffffffffu, acc, o);
        if (lane == 0) slog[e * 4 + w] = acc;
    }
    __syncthreads();

    {   // softmax
        float es = slog[E * 4 + w];
        float v;
        if (lane < E) {
            float l = es + slog[lane * 4 + w];
            v = (l >= 0.f) ? l : 0.2f * l;
        } else {
            v = -3.4e38f;
        }
        float m = v;
        #pragma unroll
        for (int o = 16; o; o >>= 1) m = fmaxf(m, __shfl_xor_sync(0xffffffffu, m, o));
        float p = (lane < E) ? __expf(v - m) : 0.f;
        float sum = p;
        #pragma unroll
        for (int o = 16; o; o >>= 1) sum += __shfl_xor_sync(0xffffffffu, sum, o);
        if (lane < E) salpha[lane * 4 + w] = p / sum;
    }
    __syncthreads();

    // aggregate: per e one float4-broadcast alpha + 4 data LDS, 16 FMA
    float acc[4][4];
    #pragma unroll
    for (int c = 0; c < 4; c++)
        #pragma unroll
        for (int q = 0; q < 4; q++) acc[c][q] = 0.f;
    #pragma unroll
    for (int e = 0; e < E; e++) {
        float4 al = lds4(&salpha[e * 4]);
        #pragma unroll
        for (int c = 0; c < 4; c++) {
            float val = sxn[e * F + c * 128 + tid];
            acc[c][0] = fmaf(al.x, val, acc[c][0]);
            acc[c][1] = fmaf(al.y, val, acc[c][1]);
            acc[c][2] = fmaf(al.z, val, acc[c][2]);
            acc[c][3] = fmaf(al.w, val, acc[c][3]);
        }
    }
    float* gy = y + (size_t)g * (4 * F);
    #pragma unroll
    for (int q = 0; q < 4; q++)
        #pragma unroll
        for (int c = 0; c < 4; c++)
            gy[q * F + c * 128 + tid] = acc[c][q];
}

// ---------------------------------------------------------------------------
extern "C" void kernel_launch(void* const* d_in, const int* in_sizes, int n_in,
                              void* d_out, int out_size)
{
    const float* h0  = (const float*)d_in[0];
    const float* h1  = (const float*)d_in[1];
    const float* h2  = (const float*)d_in[2];
    const float* W0  = (const float*)d_in[3];
    const float* a0s = (const float*)d_in[4];
    const float* a0n = (const float*)d_in[5];
    const float* W1  = (const float*)d_in[6];
    const float* a1s = (const float*)d_in[7];
    const float* a1n = (const float*)d_in[8];
    const float* Wfc = (const float*)d_in[9];
    float* out = (float*)d_out;

    float* scr = nullptr;
    cudaGetSymbolAddress((void**)&scr, g_scratch);
    float* y1   = scr + OFF_Y1;
    float* y0   = scr + OFF_Y0;
    float* u    = scr + OFF_U;
    float* hs0  = scr + OFF_H;
    float* P0   = scr + OFF_P0;
    float* Q    = scr + OFF_Q;
    float* Nmat = scr + OFF_N;

    prepN_kernel<<<dim3(4, 4, 16), 256>>>(W0, W1, Nmat);
    prepQP_kernel<<<20, 128>>>(Nmat, a1s, a1n, W0, a0s, a0n, Q, P0);

    // both F=128 attentions
    attn128_kernel<<<10240 + 1024, 128>>>(h0, h1, h2, P0, P0 + 512,
                                          y1, y0, 10240);

    // layer-1 attention -> u [1024, 4(h'), 512]
    attn512_kernel<<<1024, 128>>>(y0, y1, Q, Q + 2048, u);

    // hs0[g, hp*128+d'] = u[g,hp,:] @ N[hp]   (32x64 tiles, 256 blocks)
    gemm_kernel<<<dim3(2, 32, 4), 256>>>(u, Nmat, hs0, 512, 2048, 128, 512,
                                         512, 512 * 128, 128);
    // out = hs0 @ Wfc  (32x64 tiles, 128 blocks)
    gemm_kernel<<<dim3(4, 32, 1), 256>>>(hs0, Wfc, out, 512, 512, 256, 256,
                                         0, 0, 0);
}